// round 16
// baseline (speedup 1.0000x reference)
#include <cuda_runtime.h>
#include <cuda_fp16.h>
#include <cstdint>
#include <cstddef>

#define NB 8
#define NN 256
#define NH 64
#define NL 2
#define NA 10
#define LN_EPS 1e-5f

// fp16 SMEM stride: 72 halfs/row (144B) -> conflict-free LDSM (4r mod 32 start banks)
#define HST 72

// ---- SMEM byte offsets for k_main (layer 0, 256 rows) ----
#define OB_ES   0                       // half [256][72] = 36864B
#define OB_W4   36864                   // half [64][72]  = 9216B
#define OB_LG   46080                   // float[256]
#define OB_SALL 47104                   // float[256]
#define OB_ATT  48128                   // float[256]
#define OB_WAGG 49152                   // float[8][64]
#define OB_RED  51200                   // float[16]
#define OB_RED2 51264                   // float[16]
#define OB_EG   51328                   // float[64]
#define OB_EB   51584                   // float[64]
#define OB_W4S1 51840                   // float[64]
#define SMEM_MAIN_BYTES 52096

// ---- SMEM byte offsets for k_main1 (layer 1, 128 rows per block) ----
#define K1_ES   0                       // half [128][72] = 18432B
#define K1_W4   18432                   // half [64][72]  = 9216B
#define K1_SA   27648                   // float[256]
#define K1_ATT  28672                   // float[128]
#define K1_WAGG 29184                   // float[8][64]
#define K1_RED  31232                   // float[16]
#define K1_RED2 31296                   // float[16]
#define K1_BYTES 31360

// ---------------- device scratch ----------------
__device__ __half g_E1h[(size_t)NB*NN*NN*NH]; // 64 MB inter-layer E buffer (fp16, LN'd)
__device__ float  g_LG1[NB*NN*NN];            // 2 MB: layer-1 logit partials (fp32 exact)
__device__ float  g_Xbuf[NB*NN*NH];
__device__ __half g_XJh[NB*NN*NH];            // X @ W5^T (fp16)
__device__ float  g_XR[NB*NN*NH];             // X @ W6^T
__device__ float  g_AGG[NB*NN*NH];            // layer-0 einsum result
__device__ float  g_AGG1[2*NB*NN*NH/2];       // layer-1 halves: [4096][64]
__device__ float  g_S[NB*NN];                 // row sums of Xi (current layer)
__device__ float  g_w3s[NL*NH];
__device__ float  g_w4s[NL*NH];
__device__ int    g_dummy;

__device__ __forceinline__ uint32_t h2_bits(__half2 h) {
    return *reinterpret_cast<uint32_t*>(&h);
}

// ---------------- fp16 mma.sync m16n8k16 ----------------
__device__ __forceinline__ void mma_f16(float* c, const uint32_t* a,
                                        uint32_t b0, uint32_t b1) {
    asm volatile(
        "mma.sync.aligned.m16n8k16.row.col.f32.f16.f16.f32 "
        "{%0,%1,%2,%3}, {%4,%5,%6,%7}, {%8,%9}, {%0,%1,%2,%3};"
        : "+f"(c[0]), "+f"(c[1]), "+f"(c[2]), "+f"(c[3])
        : "r"(a[0]), "r"(a[1]), "r"(a[2]), "r"(a[3]), "r"(b0), "r"(b1));
}

__device__ __forceinline__ void ldsm_x4(uint32_t& r0, uint32_t& r1,
                                        uint32_t& r2, uint32_t& r3, uint32_t addr) {
    asm volatile("ldmatrix.sync.aligned.m8n8.x4.shared.b16 {%0,%1,%2,%3}, [%4];"
        : "=r"(r0), "=r"(r1), "=r"(r2), "=r"(r3) : "r"(addr));
}

#define CP_ASYNC16(sm, gp) \
    asm volatile("cp.async.cg.shared.global [%0], [%1], 16;" :: "r"(sm), "l"(gp) : "memory")
#define CP_COMMIT() asm volatile("cp.async.commit_group;" ::: "memory")
#define CP_WAIT0()  asm volatile("cp.async.wait_group 0;" ::: "memory")

// Halving reduce round: v[0..n) and v[n..2n) merge across lanes differing in bit b.
#define HALVE_ROUND(v, n, b)                                             \
    _Pragma("unroll")                                                    \
    for (int _c = 0; _c < (n); _c++) {                                   \
        float _lo = v[_c], _hi = v[_c + (n)];                            \
        float _send = (lane & (b)) ? _lo : _hi;                          \
        float _recv = __shfl_xor_sync(0xffffffffu, _send, (b));          \
        v[_c] = ((lane & (b)) ? _hi : _lo) + _recv;                      \
    }

// ---------------- dummy (keeps k_main in ncu's captured launch slot) ----------
__global__ void k_dummy() { if (threadIdx.x == 0) g_dummy = 1; }

// ---------------- column sums of W3 / W4 ----------------
__global__ void k_sums(const float* __restrict__ W3, const float* __restrict__ W4) {
    int t = threadIdx.x;            // 128 threads: (layer, k)
    int l = t >> 6, k = t & 63;
    float s3 = 0.f, s4 = 0.f;
    #pragma unroll 8
    for (int h = 0; h < NH; h++) {
        s3 += W3[(l*NH + h)*NH + k];
        s4 += W4[(l*NH + h)*NH + k];
    }
    g_w3s[t] = s3;
    g_w4s[t] = s4;
}

// ---------------- layer-0 X pre: s0, XJ0, XR0 (8 rows per 512-thread block) ----------
__global__ void __launch_bounds__(512) k_xstart(
    const float* __restrict__ X0, const float* __restrict__ W5,
    const float* __restrict__ W6) {
    __shared__ float W5T[NH*65];
    __shared__ float W6T[NH*65];
    __shared__ float Xs[8*NH];
    __shared__ float red[16];
    const int t = threadIdx.x, ri = t >> 6, h = t & 63;
    const int row = blockIdx.x*8 + ri;

    for (int idx = t; idx < NH*NH; idx += 512) {
        int r = idx >> 6, k = idx & 63;
        W5T[k*65 + r] = W5[idx];
        W6T[k*65 + r] = W6[idx];
    }
    Xs[t] = X0[row*NH + h];
    __syncthreads();

    float a5 = 0.f, a6 = 0.f;
    #pragma unroll 8
    for (int k = 0; k < NH; k++) {
        float x = Xs[ri*NH + k];
        a5 = fmaf(x, W5T[k*65 + h], a5);
        a6 = fmaf(x, W6T[k*65 + h], a6);
    }
    g_XJh[row*NH + h] = __float2half(a5);
    g_XR[row*NH + h]  = a6;

    float p = Xs[t] * g_w3s[h];
    #pragma unroll
    for (int o = 16; o; o >>= 1) p += __shfl_xor_sync(0xffffffffu, p, o);
    if ((t & 31) == 0) red[t >> 5] = p;
    __syncthreads();
    if (h == 0) g_S[row] = red[2*ri] + red[2*ri + 1];
}

// ---------------- mid: X1 = LN(relu(agg+XR0))+X0, then s1, XJ1, XR1 ----------------
__global__ void __launch_bounds__(512) k_xmid(
    const float* __restrict__ X0, const float* __restrict__ W5,
    const float* __restrict__ W6, const float* __restrict__ ng,
    const float* __restrict__ nb) {
    __shared__ float W5T[NH*65];
    __shared__ float W6T[NH*65];
    __shared__ float Xs[8*NH];
    __shared__ float red[16];
    __shared__ float red2[16];
    const int t = threadIdx.x, ri = t >> 6, h = t & 63;
    const int row = blockIdx.x*8 + ri;

    for (int idx = t; idx < NH*NH; idx += 512) {
        int r = idx >> 6, k = idx & 63;
        W5T[k*65 + r] = W5[NH*NH + idx];
        W6T[k*65 + r] = W6[NH*NH + idx];
    }

    float v = fmaxf(g_AGG[row*NH + h] + g_XR[row*NH + h], 0.f);
    float p = v;
    #pragma unroll
    for (int o = 16; o; o >>= 1) p += __shfl_xor_sync(0xffffffffu, p, o);
    if ((t & 31) == 0) red[t >> 5] = p;
    __syncthreads();
    float mean = (red[2*ri] + red[2*ri + 1]) * (1.f/NH);
    float d = v - mean;
    p = d*d;
    #pragma unroll
    for (int o = 16; o; o >>= 1) p += __shfl_xor_sync(0xffffffffu, p, o);
    if ((t & 31) == 0) red2[t >> 5] = p;
    __syncthreads();
    float rstd = rsqrtf((red2[2*ri] + red2[2*ri + 1]) * (1.f/NH) + LN_EPS);
    float x1 = d*rstd*ng[h] + nb[h] + X0[row*NH + h];
    g_Xbuf[row*NH + h] = x1;
    Xs[t] = x1;
    __syncthreads();

    float a5 = 0.f, a6 = 0.f;
    #pragma unroll 8
    for (int k = 0; k < NH; k++) {
        float x = Xs[ri*NH + k];
        a5 = fmaf(x, W5T[k*65 + h], a5);
        a6 = fmaf(x, W6T[k*65 + h], a6);
    }
    g_XJh[row*NH + h] = __float2half(a5);
    g_XR[row*NH + h]  = a6;

    p = x1 * g_w3s[NH + h];
    #pragma unroll
    for (int o = 16; o; o >>= 1) p += __shfl_xor_sync(0xffffffffu, p, o);
    if ((t & 31) == 0) red[t >> 5] = p;
    __syncthreads();
    if (h == 0) g_S[row] = red[2*ri] + red[2*ri + 1];
}

// ---------------- final: X2 = LN(relu(agg0+agg1+XR1))+X1, then head -> out ----------
__global__ void __launch_bounds__(512) k_final(
    const float* __restrict__ ng, const float* __restrict__ nb,
    const float* __restrict__ hw1, const float* __restrict__ hb1,
    const float* __restrict__ hw2, const float* __restrict__ hb2,
    float* __restrict__ out) {
    __shared__ float W1T[NH*65];
    __shared__ float Xs[8*NH];
    __shared__ float h1s[8*NH];
    __shared__ float red[16];
    __shared__ float red2[16];
    const int t = threadIdx.x, ri = t >> 6, h = t & 63;
    const int row = blockIdx.x*8 + ri;

    for (int idx = t; idx < NH*NH; idx += 512) {
        int r = idx >> 6, k = idx & 63;
        W1T[k*65 + r] = hw1[idx];
    }

    float aggv = g_AGG1[(2*row)*NH + h] + g_AGG1[(2*row + 1)*NH + h];
    float v = fmaxf(aggv + g_XR[row*NH + h], 0.f);
    float p = v;
    #pragma unroll
    for (int o = 16; o; o >>= 1) p += __shfl_xor_sync(0xffffffffu, p, o);
    if ((t & 31) == 0) red[t >> 5] = p;
    __syncthreads();
    float mean = (red[2*ri] + red[2*ri + 1]) * (1.f/NH);
    float d = v - mean;
    p = d*d;
    #pragma unroll
    for (int o = 16; o; o >>= 1) p += __shfl_xor_sync(0xffffffffu, p, o);
    if ((t & 31) == 0) red2[t >> 5] = p;
    __syncthreads();
    float rstd = rsqrtf((red2[2*ri] + red2[2*ri + 1]) * (1.f/NH) + LN_EPS);
    Xs[t] = d*rstd*ng[NH + h] + nb[NH + h] + g_Xbuf[row*NH + h];
    __syncthreads();

    float a = hb1[h];
    #pragma unroll 8
    for (int k = 0; k < NH; k++) a = fmaf(Xs[ri*NH + k], W1T[k*65 + h], a);
    h1s[t] = fmaxf(a, 0.f);
    __syncthreads();

    if (h < NA) {
        float o = hb2[h];
        #pragma unroll 8
        for (int k = 0; k < NH; k++) o = fmaf(h1s[ri*NH + k], hw2[h*NH + k], o);
        out[row*NA + h] = o;
    }
}

// ---------------- layer-0 main kernel (256 rows per block, 3 CTAs/SM target) --------
__global__ void __launch_bounds__(256, 3) k_main(
    const float* __restrict__ E0, const float* __restrict__ W4,
    const float* __restrict__ eg, const float* __restrict__ eb) {
    extern __shared__ char smc[];
    __half* Es16 = reinterpret_cast<__half*>(smc + OB_ES);
    __half* Wh   = reinterpret_cast<__half*>(smc + OB_W4);
    float* lgA  = reinterpret_cast<float*>(smc + OB_LG);
    float* sA   = reinterpret_cast<float*>(smc + OB_SALL);
    float* attA = reinterpret_cast<float*>(smc + OB_ATT);
    float* wagg = reinterpret_cast<float*>(smc + OB_WAGG);
    float* red  = reinterpret_cast<float*>(smc + OB_RED);
    float* red2 = reinterpret_cast<float*>(smc + OB_RED2);
    float* egs  = reinterpret_cast<float*>(smc + OB_EG);
    float* ebs  = reinterpret_cast<float*>(smc + OB_EB);
    float* w41s = reinterpret_cast<float*>(smc + OB_W4S1);

    const int bi = blockIdx.x;
    const int b  = bi >> 8;
    const int t  = threadIdx.x;
    const int w  = t >> 5;
    const int lane = t & 31;
    const int gid = lane >> 2, tig = lane & 3;

    // E load (fp32) + exact logit partials + fp16 SMEM store
    {
        const float4* Eg4 = reinterpret_cast<const float4*>(E0 + (size_t)bi*NN*NH);
        const int q = t >> 4, k4 = t & 15;
        const float4 wv = *reinterpret_cast<const float4*>(g_w4s + 4*k4);
        float part[16];
        #pragma unroll
        for (int c = 0; c < 16; c++) {
            int idx4 = t + 256*c;
            float4 v = Eg4[idx4];
            int j = idx4 >> 4;
            part[c] = v.x*wv.x + v.y*wv.y + v.z*wv.z + v.w*wv.w;
            uint2 pk;
            pk.x = h2_bits(__floats2half2_rn(v.x, v.y));
            pk.y = h2_bits(__floats2half2_rn(v.z, v.w));
            *reinterpret_cast<uint2*>(Es16 + j*HST + 4*k4) = pk;
        }
        // value-routed halving reduce over the 16-lane group: lane k4 ends with c=k4
        HALVE_ROUND(part, 8, 8);
        HALVE_ROUND(part, 4, 4);
        HALVE_ROUND(part, 2, 2);
        HALVE_ROUND(part, 1, 1);
        lgA[q + 16*k4] = part[0];
        if (t < NH) {
            egs[t]  = eg[t];
            ebs[t]  = eb[t];
            w41s[t] = g_w4s[NH + t];
        }
    }
    // W4 layer-0 slice -> fp16 SMEM
    {
        const float2* Wg2 = reinterpret_cast<const float2*>(W4);
        #pragma unroll
        for (int c = 0; c < 8; c++) {
            int idx2 = t + 256*c;
            int h = idx2 >> 5, k2 = idx2 & 31;
            float2 vw = Wg2[idx2];
            *reinterpret_cast<__half2*>(Wh + h*HST + 2*k2) = __floats2half2_rn(vw.x, vw.y);
        }
    }
    sA[t] = g_S[b*NN + t];
    __syncthreads();

    // --- block softmax over 256, 3 barriers ---
    float lg = lgA[t] + g_S[bi] + sA[t];
    float m = lg;
    #pragma unroll
    for (int o = 16; o; o >>= 1) m = fmaxf(m, __shfl_xor_sync(0xffffffffu, m, o));
    if (lane == 0) red[w] = m;
    __syncthreads();
    float mm = red[0];
    #pragma unroll
    for (int q = 1; q < 8; q++) mm = fmaxf(mm, red[q]);
    float ex = __expf(lg - mm);
    float sum = ex;
    #pragma unroll
    for (int o = 16; o; o >>= 1) sum += __shfl_xor_sync(0xffffffffu, sum, o);
    if (lane == 0) red2[w] = sum;
    __syncthreads();
    float s8 = 0.f;
    #pragma unroll
    for (int q = 0; q < 8; q++) s8 += red2[q];
    attA[t] = ex / s8;
    __syncthreads();

    // --- per-mt: fp16 tensor GEMM (acc[8][4] live) + fragment epilogue ---
    float aggp[16];
    #pragma unroll
    for (int z = 0; z < 16; z++) aggp[z] = 0.f;
    float* LG1o = g_LG1 + (size_t)bi*NN;
    const __half2* XJg2 = reinterpret_cast<const __half2*>(g_XJh + (size_t)b*NN*NH);

    const uint32_t es_sh = (uint32_t)__cvta_generic_to_shared(Es16);
    const uint32_t wh_sh = (uint32_t)__cvta_generic_to_shared(Wh);
    const int l15 = lane & 15;
    const int lhi = lane >> 4;
    const int l7  = lane & 7;
    const int bsl = (lane >> 3) & 1;
    const uint32_t bAddr = wh_sh + (uint32_t)((l7 + 8*lhi)*144 + bsl*16);

    #pragma unroll
    for (int mt = 0; mt < 2; mt++) {
        float acc[8][4];
        #pragma unroll
        for (int nt = 0; nt < 8; nt++)
            #pragma unroll
            for (int q = 0; q < 4; q++) acc[nt][q] = 0.f;

        const uint32_t aAddr = es_sh + (uint32_t)((w*32 + mt*16 + l15)*144 + lhi*16);
        #pragma unroll
        for (int ks = 0; ks < 4; ks++) {
            uint32_t a[4];
            ldsm_x4(a[0], a[1], a[2], a[3], aAddr + 32*ks);
            #pragma unroll
            for (int p = 0; p < 4; p++) {
                uint32_t b0a, b1a, b0b, b1b;
                ldsm_x4(b0a, b1a, b0b, b1b, bAddr + p*16*144 + 32*ks);
                mma_f16(acc[2*p],     a, b0a, b1a);
                mma_f16(acc[2*p + 1], a, b0b, b1b);
            }
        }

        const int rA = w*32 + mt*16 + gid;
        const int rB = rA + 8;
        const float aA = attA[rA], aB = attA[rB];
        float s0 = 0.f, q0 = 0.f, s1 = 0.f, q1 = 0.f;
        #pragma unroll
        for (int nt = 0; nt < 8; nt++) {
            float e0 = acc[nt][0] * aA;
            float e1 = acc[nt][1] * aA;
            float e2 = acc[nt][2] * aB;
            float e3 = acc[nt][3] * aB;
            acc[nt][0] = e0; acc[nt][1] = e1;
            acc[nt][2] = e2; acc[nt][3] = e3;
            const int hc = nt*8 + 2*tig;
            float2 xA = __half22float2(XJg2[(rA*NH + hc) >> 1]);
            float2 xB = __half22float2(XJg2[(rB*NH + hc) >> 1]);
            aggp[2*nt]     += e0*xA.x + e2*xB.x;
            aggp[2*nt + 1] += e1*xA.y + e3*xB.y;
            s0 += e0 + e1; q0 += e0*e0 + e1*e1;
            s1 += e2 + e3; q1 += e2*e2 + e3*e3;
        }
        #pragma unroll
        for (int o = 1; o <= 2; o <<= 1) {
            s0 += __shfl_xor_sync(0xffffffffu, s0, o);
            q0 += __shfl_xor_sync(0xffffffffu, q0, o);
            s1 += __shfl_xor_sync(0xffffffffu, s1, o);
            q1 += __shfl_xor_sync(0xffffffffu, q1, o);
        }
        const float mA = s0 * (1.f/NH);
        const float rsA = rsqrtf(fmaf(q0, 1.f/NH, -mA*mA) + LN_EPS);
        const float mB = s1 * (1.f/NH);
        const float rsB = rsqrtf(fmaf(q1, 1.f/NH, -mB*mB) + LN_EPS);
        float lpA = 0.f, lpB = 0.f;
        #pragma unroll
        for (int nt = 0; nt < 8; nt++) {
            const int hc = nt*8 + 2*tig;
            const float2 g2 = *reinterpret_cast<const float2*>(egs + hc);
            const float2 b2 = *reinterpret_cast<const float2*>(ebs + hc);
            float vA0 = (acc[nt][0] - mA)*rsA*g2.x + b2.x;
            float vA1 = (acc[nt][1] - mA)*rsA*g2.y + b2.y;
            float vB0 = (acc[nt][2] - mB)*rsB*g2.x + b2.x;
            float vB1 = (acc[nt][3] - mB)*rsB*g2.y + b2.y;
            *reinterpret_cast<__half2*>(Es16 + rA*HST + hc) = __floats2half2_rn(vA0, vA1);
            *reinterpret_cast<__half2*>(Es16 + rB*HST + hc) = __floats2half2_rn(vB0, vB1);
            const float2 w2 = *reinterpret_cast<const float2*>(w41s + hc);
            lpA += vA0*w2.x + vA1*w2.y;
            lpB += vB0*w2.x + vB1*w2.y;
        }
        #pragma unroll
        for (int o = 1; o <= 2; o <<= 1) {
            lpA += __shfl_xor_sync(0xffffffffu, lpA, o);
            lpB += __shfl_xor_sync(0xffffffffu, lpB, o);
        }
        if (tig == 0) {
            LG1o[rA] = lpA;
            LG1o[rB] = lpB;
        }
    }

    // --- agg halving reduce over gid lanes (xor 4/8/16); every lane stores 2 ---
    HALVE_ROUND(aggp, 8, 4);
    HALVE_ROUND(aggp, 4, 8);
    HALVE_ROUND(aggp, 2, 16);
    {
        const int nt8 = 4*((lane >> 2) & 1) + 2*((lane >> 3) & 1) + ((lane >> 4) & 1);
        float2 v2 = {aggp[0], aggp[1]};
        *reinterpret_cast<float2*>(wagg + w*64 + nt8*8 + 2*tig) = v2;
    }
    __syncthreads();   // E1 write-out reads ALL warps' Es16 rows

    if (t < NH) {
        float s = 0.f;
        #pragma unroll
        for (int q = 0; q < 8; q++) s += wagg[q*64 + t];
        g_AGG[bi*NH + t] = s;
    }
    // coalesced E1 write-out from staged SMEM
    {
        uint4* Eo = reinterpret_cast<uint4*>(g_E1h + (size_t)bi*NN*NH);
        #pragma unroll
        for (int c = 0; c < 8; c++) {
            int idx = t + 256*c;
            int j = idx >> 3, q = idx & 7;
            Eo[idx] = *reinterpret_cast<const uint4*>(Es16 + j*HST + q*8);
        }
    }
}

// ---------------- layer-1 main kernel (128 rows per block, 4 CTAs/SM target) --------
__global__ void __launch_bounds__(256, 4) k_main1(const float* __restrict__ W4) {
    extern __shared__ char smc[];
    __half* Es16 = reinterpret_cast<__half*>(smc + K1_ES);
    __half* Wh   = reinterpret_cast<__half*>(smc + K1_W4);
    float* sA   = reinterpret_cast<float*>(smc + K1_SA);
    float* attA = reinterpret_cast<float*>(smc + K1_ATT);
    float* wagg = reinterpret_cast<float*>(smc + K1_WAGG);
    float* red  = reinterpret_cast<float*>(smc + K1_RED);
    float* red2 = reinterpret_cast<float*>(smc + K1_RED2);

    const int bi   = blockIdx.x >> 1;
    const int half = blockIdx.x & 1;
    const int b  = bi >> 8;
    const int t  = threadIdx.x;
    const int w  = t >> 5;
    const int lane = t & 31;
    const int gid = lane >> 2, tig = lane & 3;

    // E1 half-slab load: pure copy -> cp.async (overlap with softmax)
    {
        const uint32_t es_sh = (uint32_t)__cvta_generic_to_shared(Es16);
        const __half* Eg = g_E1h + (size_t)bi*NN*NH + (size_t)half*128*NH;
        #pragma unroll
        for (int c = 0; c < 4; c++) {
            int idx = t + 256*c;
            int j = idx >> 3, q = idx & 7;
            CP_ASYNC16(es_sh + (uint32_t)(j*HST + q*8)*2, Eg + (size_t)idx*8);
        }
        CP_COMMIT();
    }
    // W4 layer-1 slice -> fp16 SMEM (needs conversion; sync loads)
    {
        const float2* Wg2 = reinterpret_cast<const float2*>(W4 + NH*NH);
        #pragma unroll
        for (int c = 0; c < 8; c++) {
            int idx2 = t + 256*c;
            int h = idx2 >> 5, k2 = idx2 & 31;
            float2 vw = Wg2[idx2];
            *reinterpret_cast<__half2*>(Wh + h*HST + 2*k2) = __floats2half2_rn(vw.x, vw.y);
        }
    }
    sA[t] = g_S[b*NN + t];
    __syncthreads();

    // --- softmax over all 256 j (logits precomputed), overlapped with cp.async ---
    float lg = g_LG1[(size_t)bi*NN + t] + g_S[bi] + sA[t];
    float m = lg;
    #pragma unroll
    for (int o = 16; o; o >>= 1) m = fmaxf(m, __shfl_xor_sync(0xffffffffu, m, o));
    if (lane == 0) red[w] = m;
    __syncthreads();
    float mm = red[0];
    #pragma unroll
    for (int q = 1; q < 8; q++) mm = fmaxf(mm, red[q]);
    float ex = __expf(lg - mm);
    float sum = ex;
    #pragma unroll
    for (int o = 16; o; o >>= 1) sum += __shfl_xor_sync(0xffffffffu, sum, o);
    if (lane == 0) red2[w] = sum;
    __syncthreads();
    float s8 = 0.f;
    #pragma unroll
    for (int q = 0; q < 8; q++) s8 += red2[q];
    if ((t >> 7) == half) attA[t & 127] = ex / s8;
    CP_WAIT0();              // E1 staged before the barrier below
    __syncthreads();

    // --- fp16 tensor GEMM via ldmatrix: warp w -> local rows [w*16, w*16+16) ---
    float acc[8][4];
    #pragma unroll
    for (int nt = 0; nt < 8; nt++)
        #pragma unroll
        for (int q = 0; q < 4; q++) acc[nt][q] = 0.f;

    {
        const uint32_t es_sh = (uint32_t)__cvta_generic_to_shared(Es16);
        const uint32_t wh_sh = (uint32_t)__cvta_generic_to_shared(Wh);
        const int l15 = lane & 15;
        const int lhi = lane >> 4;
        const int l7  = lane & 7;
        const int bsl = (lane >> 3) & 1;
        const uint32_t aAddr = es_sh + (uint32_t)((w*16 + l15)*144 + lhi*16);
        const uint32_t bAddr = wh_sh + (uint32_t)((l7 + 8*lhi)*144 + bsl*16);
        #pragma unroll
        for (int ks = 0; ks < 4; ks++) {
            uint32_t a[4];
            ldsm_x4(a[0], a[1], a[2], a[3], aAddr + 32*ks);
            #pragma unroll
            for (int p = 0; p < 4; p++) {
                uint32_t b0a, b1a, b0b, b1b;
                ldsm_x4(b0a, b1a, b0b, b1b, bAddr + p*16*144 + 32*ks);
                mma_f16(acc[2*p],     a, b0a, b1a);
                mma_f16(acc[2*p + 1], a, b0b, b1b);
            }
        }
    }

    // --- epilogue: att scale + fragment agg (XJ direct from global, L2-hot) ---
    float aggp[16];
    #pragma unroll
    for (int z = 0; z < 16; z++) aggp[z] = 0.f;
    {
        const int rA = w*16 + gid;
        const int rB = rA + 8;
        const float aA = attA[rA], aB = attA[rB];
        const __half2* XJg2 = reinterpret_cast<const __half2*>(
            g_XJh + (size_t)b*NN*NH + (size_t)half*128*NH);
        #pragma unroll
        for (int nt = 0; nt < 8; nt++) {
            float e0 = acc[nt][0] * aA;
            float e1 = acc[nt][1] * aA;
            float e2 = acc[nt][2] * aB;
            float e3 = acc[nt][3] * aB;
            const int hc = nt*8 + 2*tig;
            float2 xA = __half22float2(XJg2[(rA*NH + hc) >> 1]);
            float2 xB = __half22float2(XJg2[(rB*NH + hc) >> 1]);
            aggp[2*nt]     += e0*xA.x + e2*xB.x;
            aggp[2*nt + 1] += e1*xA.y + e3*xB.y;
        }
    }
    // halving reduce over gid lanes (xor 4/8/16); every lane stores 2 floats
    HALVE_ROUND(aggp, 8, 4);
    HALVE_ROUND(aggp, 4, 8);
    HALVE_ROUND(aggp, 2, 16);
    {
        const int nt8 = 4*((lane >> 2) & 1) + 2*((lane >> 3) & 1) + ((lane >> 4) & 1);
        float2 v2 = {aggp[0], aggp[1]};
        *reinterpret_cast<float2*>(wagg + w*64 + nt8*8 + 2*tig) = v2;
    }
    __syncthreads();
    if (t < NH) {
        float s = 0.f;
        #pragma unroll
        for (int q = 0; q < 8; q++) s += wagg[q*64 + t];
        g_AGG1[blockIdx.x*NH + t] = s;
    }
}

// ---------------- launch ----------------
extern "C" void kernel_launch(void* const* d_in, const int* in_sizes, int n_in,
                              void* d_out, int out_size) {
    const float* X   = (const float*)d_in[0];
    const float* E   = (const float*)d_in[1];
    const float* W3  = (const float*)d_in[2];
    const float* W4  = (const float*)d_in[3];
    const float* W5  = (const float*)d_in[4];
    const float* W6  = (const float*)d_in[5];
    const float* ng  = (const float*)d_in[6];
    const float* nb  = (const float*)d_in[7];
    const float* eg  = (const float*)d_in[8];
    const float* eb  = (const float*)d_in[9];
    const float* hw1 = (const float*)d_in[10];
    const float* hb1 = (const float*)d_in[11];
    const float* hw2 = (const float*)d_in[12];
    const float* hb2 = (const float*)d_in[13];
    float* out = (float*)d_out;

    cudaFuncSetAttribute(k_main, cudaFuncAttributeMaxDynamicSharedMemorySize,
                         SMEM_MAIN_BYTES);
    cudaFuncSetAttribute(k_main1, cudaFuncAttributeMaxDynamicSharedMemorySize,
                         K1_BYTES);

    k_dummy<<<1, 32>>>();                       // keeps k_main in ncu capture slot
    k_sums<<<1, 128>>>(W3, W4);
    k_xstart<<<NB*NN/8, 512>>>(X, W5, W6);
    k_main<<<NB*NN, 256, SMEM_MAIN_BYTES>>>(E, W4, eg, eb);
    k_xmid<<<NB*NN/8, 512>>>(X, W5, W6, ng, nb);
    k_main1<<<2*NB*NN, 256, K1_BYTES>>>(W4);
    k_final<<<NB*NN/8, 512>>>(ng, nb, hw1, hb1, hw2, hb2, out);
}

// round 17
// speedup vs baseline: 1.0781x; 1.0781x over previous
#include <cuda_runtime.h>
#include <cuda_fp16.h>
#include <cstdint>
#include <cstddef>

#define NB 8
#define NN 256
#define NH 64
#define NL 2
#define NA 10
#define LN_EPS 1e-5f

// fp16 SMEM stride: 72 halfs/row (144B) -> conflict-free LDSM (4r mod 32 start banks)
#define HST 72

// ---- SMEM byte offsets for k_main (layer 0, 256 rows) ----
#define OB_ES   0                       // half [256][72] = 36864B
#define OB_W4   36864                   // half [64][72]  = 9216B
#define OB_XJ   46080                   // half [256][72] = 36864B
#define OB_LG   82944                   // float[256]
#define OB_SALL 83968                   // float[256]
#define OB_ATT  84992                   // float[256]
#define OB_WAGG 86016                   // float[8][64]
#define OB_RED  88064                   // float[16]
#define OB_RED2 88128                   // float[16]
#define OB_EG   88192                   // float[64]
#define OB_EB   88448                   // float[64]
#define OB_W4S1 88704                   // float[64]
#define SMEM_MAIN_BYTES 88960

// ---- SMEM byte offsets for k_main1 (layer 1, 128 rows per block) ----
#define K1_ES   0                       // half [128][72] = 18432B
#define K1_W4   18432                   // half [64][72]  = 9216B
#define K1_XJ   27648                   // half [128][72] = 18432B
#define K1_SA   46080                   // float[256]
#define K1_ATT  47104                   // float[128]
#define K1_WAGG 47616                   // float[8][64]
#define K1_RED  49664                   // float[16]
#define K1_RED2 49728                   // float[16]
#define K1_BYTES 49792

// ---------------- device scratch ----------------
__device__ __half g_E1h[(size_t)NB*NN*NN*NH]; // 64 MB inter-layer E buffer (fp16, LN'd)
__device__ float  g_LG1[NB*NN*NN];            // 2 MB: layer-1 logit partials (fp32 exact)
__device__ float  g_Xbuf[NB*NN*NH];
__device__ __half g_XJh[NB*NN*NH];            // X @ W5^T (fp16)
__device__ float  g_XR[NB*NN*NH];             // X @ W6^T
__device__ float  g_AGG[NB*NN*NH];            // layer-0 einsum result
__device__ float  g_AGG1[2*NB*NN*NH/2];       // layer-1 halves: [4096][64]
__device__ float  g_S[NB*NN];                 // row sums of Xi (current layer)
__device__ float  g_w3s[NL*NH];
__device__ float  g_w4s[NL*NH];
__device__ int    g_dummy;

__device__ __forceinline__ uint32_t h2_bits(__half2 h) {
    return *reinterpret_cast<uint32_t*>(&h);
}

// ---------------- fp16 mma.sync m16n8k16 ----------------
__device__ __forceinline__ void mma_f16(float* c, const uint32_t* a,
                                        uint32_t b0, uint32_t b1) {
    asm volatile(
        "mma.sync.aligned.m16n8k16.row.col.f32.f16.f16.f32 "
        "{%0,%1,%2,%3}, {%4,%5,%6,%7}, {%8,%9}, {%0,%1,%2,%3};"
        : "+f"(c[0]), "+f"(c[1]), "+f"(c[2]), "+f"(c[3])
        : "r"(a[0]), "r"(a[1]), "r"(a[2]), "r"(a[3]), "r"(b0), "r"(b1));
}

__device__ __forceinline__ void ldsm_x4(uint32_t& r0, uint32_t& r1,
                                        uint32_t& r2, uint32_t& r3, uint32_t addr) {
    asm volatile("ldmatrix.sync.aligned.m8n8.x4.shared.b16 {%0,%1,%2,%3}, [%4];"
        : "=r"(r0), "=r"(r1), "=r"(r2), "=r"(r3) : "r"(addr));
}

#define CP_ASYNC16(sm, gp) \
    asm volatile("cp.async.cg.shared.global [%0], [%1], 16;" :: "r"(sm), "l"(gp) : "memory")
#define CP_COMMIT() asm volatile("cp.async.commit_group;" ::: "memory")
#define CP_WAIT0()  asm volatile("cp.async.wait_group 0;" ::: "memory")

// Halving reduce round: v[0..n) and v[n..2n) merge across lanes differing in bit b.
#define HALVE_ROUND(v, n, b)                                             \
    _Pragma("unroll")                                                    \
    for (int _c = 0; _c < (n); _c++) {                                   \
        float _lo = v[_c], _hi = v[_c + (n)];                            \
        float _send = (lane & (b)) ? _lo : _hi;                          \
        float _recv = __shfl_xor_sync(0xffffffffu, _send, (b));          \
        v[_c] = ((lane & (b)) ? _hi : _lo) + _recv;                      \
    }

// ---------------- dummy (keeps k_main in ncu's captured launch slot) ----------
__global__ void k_dummy() { if (threadIdx.x == 0) g_dummy = 1; }

// ---------------- column sums of W3 / W4 ----------------
__global__ void k_sums(const float* __restrict__ W3, const float* __restrict__ W4) {
    int t = threadIdx.x;            // 128 threads: (layer, k)
    int l = t >> 6, k = t & 63;
    float s3 = 0.f, s4 = 0.f;
    #pragma unroll 8
    for (int h = 0; h < NH; h++) {
        s3 += W3[(l*NH + h)*NH + k];
        s4 += W4[(l*NH + h)*NH + k];
    }
    g_w3s[t] = s3;
    g_w4s[t] = s4;
}

// ---------------- layer-0 X pre: s0, XJ0, XR0 (8 rows per 512-thread block) ----------
__global__ void __launch_bounds__(512) k_xstart(
    const float* __restrict__ X0, const float* __restrict__ W5,
    const float* __restrict__ W6) {
    __shared__ float W5T[NH*65];
    __shared__ float W6T[NH*65];
    __shared__ float Xs[8*NH];
    __shared__ float red[16];
    const int t = threadIdx.x, ri = t >> 6, h = t & 63;
    const int row = blockIdx.x*8 + ri;

    for (int idx = t; idx < NH*NH; idx += 512) {
        int r = idx >> 6, k = idx & 63;
        W5T[k*65 + r] = W5[idx];
        W6T[k*65 + r] = W6[idx];
    }
    Xs[t] = X0[row*NH + h];
    __syncthreads();

    float a5 = 0.f, a6 = 0.f;
    #pragma unroll 8
    for (int k = 0; k < NH; k++) {
        float x = Xs[ri*NH + k];
        a5 = fmaf(x, W5T[k*65 + h], a5);
        a6 = fmaf(x, W6T[k*65 + h], a6);
    }
    g_XJh[row*NH + h] = __float2half(a5);
    g_XR[row*NH + h]  = a6;

    float p = Xs[t] * g_w3s[h];
    #pragma unroll
    for (int o = 16; o; o >>= 1) p += __shfl_xor_sync(0xffffffffu, p, o);
    if ((t & 31) == 0) red[t >> 5] = p;
    __syncthreads();
    if (h == 0) g_S[row] = red[2*ri] + red[2*ri + 1];
}

// ---------------- mid: X1 = LN(relu(agg+XR0))+X0, then s1, XJ1, XR1 ----------------
__global__ void __launch_bounds__(512) k_xmid(
    const float* __restrict__ X0, const float* __restrict__ W5,
    const float* __restrict__ W6, const float* __restrict__ ng,
    const float* __restrict__ nb) {
    __shared__ float W5T[NH*65];
    __shared__ float W6T[NH*65];
    __shared__ float Xs[8*NH];
    __shared__ float red[16];
    __shared__ float red2[16];
    const int t = threadIdx.x, ri = t >> 6, h = t & 63;
    const int row = blockIdx.x*8 + ri;

    for (int idx = t; idx < NH*NH; idx += 512) {
        int r = idx >> 6, k = idx & 63;
        W5T[k*65 + r] = W5[NH*NH + idx];
        W6T[k*65 + r] = W6[NH*NH + idx];
    }

    float v = fmaxf(g_AGG[row*NH + h] + g_XR[row*NH + h], 0.f);
    float p = v;
    #pragma unroll
    for (int o = 16; o; o >>= 1) p += __shfl_xor_sync(0xffffffffu, p, o);
    if ((t & 31) == 0) red[t >> 5] = p;
    __syncthreads();
    float mean = (red[2*ri] + red[2*ri + 1]) * (1.f/NH);
    float d = v - mean;
    p = d*d;
    #pragma unroll
    for (int o = 16; o; o >>= 1) p += __shfl_xor_sync(0xffffffffu, p, o);
    if ((t & 31) == 0) red2[t >> 5] = p;
    __syncthreads();
    float rstd = rsqrtf((red2[2*ri] + red2[2*ri + 1]) * (1.f/NH) + LN_EPS);
    float x1 = d*rstd*ng[h] + nb[h] + X0[row*NH + h];
    g_Xbuf[row*NH + h] = x1;
    Xs[t] = x1;
    __syncthreads();

    float a5 = 0.f, a6 = 0.f;
    #pragma unroll 8
    for (int k = 0; k < NH; k++) {
        float x = Xs[ri*NH + k];
        a5 = fmaf(x, W5T[k*65 + h], a5);
        a6 = fmaf(x, W6T[k*65 + h], a6);
    }
    g_XJh[row*NH + h] = __float2half(a5);
    g_XR[row*NH + h]  = a6;

    p = x1 * g_w3s[NH + h];
    #pragma unroll
    for (int o = 16; o; o >>= 1) p += __shfl_xor_sync(0xffffffffu, p, o);
    if ((t & 31) == 0) red[t >> 5] = p;
    __syncthreads();
    if (h == 0) g_S[row] = red[2*ri] + red[2*ri + 1];
}

// ---------------- final: X2 = LN(relu(agg0+agg1+XR1))+X1, then head -> out ----------
__global__ void __launch_bounds__(512) k_final(
    const float* __restrict__ ng, const float* __restrict__ nb,
    const float* __restrict__ hw1, const float* __restrict__ hb1,
    const float* __restrict__ hw2, const float* __restrict__ hb2,
    float* __restrict__ out) {
    __shared__ float W1T[NH*65];
    __shared__ float Xs[8*NH];
    __shared__ float h1s[8*NH];
    __shared__ float red[16];
    __shared__ float red2[16];
    const int t = threadIdx.x, ri = t >> 6, h = t & 63;
    const int row = blockIdx.x*8 + ri;

    for (int idx = t; idx < NH*NH; idx += 512) {
        int r = idx >> 6, k = idx & 63;
        W1T[k*65 + r] = hw1[idx];
    }

    float aggv = g_AGG1[(2*row)*NH + h] + g_AGG1[(2*row + 1)*NH + h];
    float v = fmaxf(aggv + g_XR[row*NH + h], 0.f);
    float p = v;
    #pragma unroll
    for (int o = 16; o; o >>= 1) p += __shfl_xor_sync(0xffffffffu, p, o);
    if ((t & 31) == 0) red[t >> 5] = p;
    __syncthreads();
    float mean = (red[2*ri] + red[2*ri + 1]) * (1.f/NH);
    float d = v - mean;
    p = d*d;
    #pragma unroll
    for (int o = 16; o; o >>= 1) p += __shfl_xor_sync(0xffffffffu, p, o);
    if ((t & 31) == 0) red2[t >> 5] = p;
    __syncthreads();
    float rstd = rsqrtf((red2[2*ri] + red2[2*ri + 1]) * (1.f/NH) + LN_EPS);
    Xs[t] = d*rstd*ng[NH + h] + nb[NH + h] + g_Xbuf[row*NH + h];
    __syncthreads();

    float a = hb1[h];
    #pragma unroll 8
    for (int k = 0; k < NH; k++) a = fmaf(Xs[ri*NH + k], W1T[k*65 + h], a);
    h1s[t] = fmaxf(a, 0.f);
    __syncthreads();

    if (h < NA) {
        float o = hb2[h];
        #pragma unroll 8
        for (int k = 0; k < NH; k++) o = fmaf(h1s[ri*NH + k], hw2[h*NH + k], o);
        out[row*NA + h] = o;
    }
}

// ---------------- layer-0 main kernel (256 rows per block; R15-exact) ----------------
__global__ void __launch_bounds__(256, 2) k_main(
    const float* __restrict__ E0, const float* __restrict__ W4,
    const float* __restrict__ eg, const float* __restrict__ eb) {
    extern __shared__ char smc[];
    __half* Es16 = reinterpret_cast<__half*>(smc + OB_ES);
    __half* Wh   = reinterpret_cast<__half*>(smc + OB_W4);
    __half* XJs  = reinterpret_cast<__half*>(smc + OB_XJ);
    float* lgA  = reinterpret_cast<float*>(smc + OB_LG);
    float* sA   = reinterpret_cast<float*>(smc + OB_SALL);
    float* attA = reinterpret_cast<float*>(smc + OB_ATT);
    float* wagg = reinterpret_cast<float*>(smc + OB_WAGG);
    float* red  = reinterpret_cast<float*>(smc + OB_RED);
    float* red2 = reinterpret_cast<float*>(smc + OB_RED2);
    float* egs  = reinterpret_cast<float*>(smc + OB_EG);
    float* ebs  = reinterpret_cast<float*>(smc + OB_EB);
    float* w41s = reinterpret_cast<float*>(smc + OB_W4S1);

    const int bi = blockIdx.x;
    const int b  = bi >> 8;
    const int t  = threadIdx.x;
    const int w  = t >> 5;
    const int lane = t & 31;
    const int gid = lane >> 2, tig = lane & 3;

    // E load (fp32) + exact logit partials + fp16 SMEM store
    {
        const float4* Eg4 = reinterpret_cast<const float4*>(E0 + (size_t)bi*NN*NH);
        const int q = t >> 4, k4 = t & 15;
        const float4 wv = *reinterpret_cast<const float4*>(g_w4s + 4*k4);
        float part[16];
        #pragma unroll
        for (int c = 0; c < 16; c++) {
            int idx4 = t + 256*c;
            float4 v = Eg4[idx4];
            int j = idx4 >> 4;
            part[c] = v.x*wv.x + v.y*wv.y + v.z*wv.z + v.w*wv.w;
            uint2 pk;
            pk.x = h2_bits(__floats2half2_rn(v.x, v.y));
            pk.y = h2_bits(__floats2half2_rn(v.z, v.w));
            *reinterpret_cast<uint2*>(Es16 + j*HST + 4*k4) = pk;
        }
        HALVE_ROUND(part, 8, 8);
        HALVE_ROUND(part, 4, 4);
        HALVE_ROUND(part, 2, 2);
        HALVE_ROUND(part, 1, 1);
        lgA[q + 16*k4] = part[0];
        if (t < NH) {
            egs[t]  = eg[t];
            ebs[t]  = eb[t];
            w41s[t] = g_w4s[NH + t];
        }
    }
    // W4 layer-0 slice -> fp16 SMEM
    {
        const float2* Wg2 = reinterpret_cast<const float2*>(W4);
        #pragma unroll
        for (int c = 0; c < 8; c++) {
            int idx2 = t + 256*c;
            int h = idx2 >> 5, k2 = idx2 & 31;
            float2 vw = Wg2[idx2];
            *reinterpret_cast<__half2*>(Wh + h*HST + 2*k2) = __floats2half2_rn(vw.x, vw.y);
        }
    }
    // XJ stage: 32KB async (consumed only in epilogue; waited before att barrier)
    {
        const uint32_t xj_sh = (uint32_t)__cvta_generic_to_shared(XJs);
        const __half* XJg = g_XJh + (size_t)b*NN*NH;
        #pragma unroll
        for (int c = 0; c < 8; c++) {
            int idx = t + 256*c;
            int j = idx >> 3, q = idx & 7;
            CP_ASYNC16(xj_sh + (uint32_t)(j*HST + q*8)*2, XJg + (size_t)idx*8);
        }
        CP_COMMIT();
    }
    sA[t] = g_S[b*NN + t];
    __syncthreads();

    // --- block softmax over 256, 3 barriers ---
    float lg = lgA[t] + g_S[bi] + sA[t];
    float m = lg;
    #pragma unroll
    for (int o = 16; o; o >>= 1) m = fmaxf(m, __shfl_xor_sync(0xffffffffu, m, o));
    if (lane == 0) red[w] = m;
    __syncthreads();
    float mm = red[0];
    #pragma unroll
    for (int q = 1; q < 8; q++) mm = fmaxf(mm, red[q]);
    float ex = __expf(lg - mm);
    float sum = ex;
    #pragma unroll
    for (int o = 16; o; o >>= 1) sum += __shfl_xor_sync(0xffffffffu, sum, o);
    if (lane == 0) red2[w] = sum;
    __syncthreads();
    float s8 = 0.f;
    #pragma unroll
    for (int q = 0; q < 8; q++) s8 += red2[q];
    attA[t] = ex / s8;
    CP_WAIT0();              // XJ staged before the barrier below
    __syncthreads();

    // --- fp16 tensor GEMM via ldmatrix: warp w -> rows [w*32, w*32+32) ---
    float acc[2][8][4];
    #pragma unroll
    for (int mt = 0; mt < 2; mt++)
        #pragma unroll
        for (int nt = 0; nt < 8; nt++)
            #pragma unroll
            for (int q = 0; q < 4; q++) acc[mt][nt][q] = 0.f;

    {
        const uint32_t es_sh = (uint32_t)__cvta_generic_to_shared(Es16);
        const uint32_t wh_sh = (uint32_t)__cvta_generic_to_shared(Wh);
        const int l15 = lane & 15;
        const int lhi = lane >> 4;
        const int l7  = lane & 7;
        const int bsl = (lane >> 3) & 1;
        const uint32_t aAddr0 = es_sh + (uint32_t)((w*32 + l15)*144 + lhi*16);
        const uint32_t aAddr1 = aAddr0 + 16*144;
        const uint32_t bAddr  = wh_sh + (uint32_t)((l7 + 8*lhi)*144 + bsl*16);
        #pragma unroll
        for (int ks = 0; ks < 4; ks++) {
            uint32_t a0[4], a1[4];
            ldsm_x4(a0[0], a0[1], a0[2], a0[3], aAddr0 + 32*ks);
            ldsm_x4(a1[0], a1[1], a1[2], a1[3], aAddr1 + 32*ks);
            #pragma unroll
            for (int p = 0; p < 4; p++) {
                uint32_t b0a, b1a, b0b, b1b;
                ldsm_x4(b0a, b1a, b0b, b1b, bAddr + p*16*144 + 32*ks);
                mma_f16(acc[0][2*p],     a0, b0a, b1a);
                mma_f16(acc[1][2*p],     a1, b0a, b1a);
                mma_f16(acc[0][2*p + 1], a0, b0b, b1b);
                mma_f16(acc[1][2*p + 1], a1, b0b, b1b);
            }
        }
    }

    // --- fragment epilogue (each warp writes its own Es16 rows) ---
    float aggp[16];
    #pragma unroll
    for (int z = 0; z < 16; z++) aggp[z] = 0.f;
    float* LG1o = g_LG1 + (size_t)bi*NN;

    #pragma unroll
    for (int mt = 0; mt < 2; mt++) {
        const int rA = w*32 + mt*16 + gid;
        const int rB = rA + 8;
        const float aA = attA[rA], aB = attA[rB];
        float s0 = 0.f, q0 = 0.f, s1 = 0.f, q1 = 0.f;
        #pragma unroll
        for (int nt = 0; nt < 8; nt++) {
            float e0 = acc[mt][nt][0] * aA;
            float e1 = acc[mt][nt][1] * aA;
            float e2 = acc[mt][nt][2] * aB;
            float e3 = acc[mt][nt][3] * aB;
            acc[mt][nt][0] = e0; acc[mt][nt][1] = e1;
            acc[mt][nt][2] = e2; acc[mt][nt][3] = e3;
            const int hc = nt*8 + 2*tig;
            float2 xA = __half22float2(*reinterpret_cast<const __half2*>(XJs + rA*HST + hc));
            float2 xB = __half22float2(*reinterpret_cast<const __half2*>(XJs + rB*HST + hc));
            aggp[2*nt]     += e0*xA.x + e2*xB.x;
            aggp[2*nt + 1] += e1*xA.y + e3*xB.y;
            s0 += e0 + e1; q0 += e0*e0 + e1*e1;
            s1 += e2 + e3; q1 += e2*e2 + e3*e3;
        }
        #pragma unroll
        for (int o = 1; o <= 2; o <<= 1) {
            s0 += __shfl_xor_sync(0xffffffffu, s0, o);
            q0 += __shfl_xor_sync(0xffffffffu, q0, o);
            s1 += __shfl_xor_sync(0xffffffffu, s1, o);
            q1 += __shfl_xor_sync(0xffffffffu, q1, o);
        }
        const float mA = s0 * (1.f/NH);
        const float rsA = rsqrtf(fmaf(q0, 1.f/NH, -mA*mA) + LN_EPS);
        const float mB = s1 * (1.f/NH);
        const float rsB = rsqrtf(fmaf(q1, 1.f/NH, -mB*mB) + LN_EPS);
        float lpA = 0.f, lpB = 0.f;
        #pragma unroll
        for (int nt = 0; nt < 8; nt++) {
            const int hc = nt*8 + 2*tig;
            const float2 g2 = *reinterpret_cast<const float2*>(egs + hc);
            const float2 b2 = *reinterpret_cast<const float2*>(ebs + hc);
            float vA0 = (acc[mt][nt][0] - mA)*rsA*g2.x + b2.x;
            float vA1 = (acc[mt][nt][1] - mA)*rsA*g2.y + b2.y;
            float vB0 = (acc[mt][nt][2] - mB)*rsB*g2.x + b2.x;
            float vB1 = (acc[mt][nt][3] - mB)*rsB*g2.y + b2.y;
            *reinterpret_cast<__half2*>(Es16 + rA*HST + hc) = __floats2half2_rn(vA0, vA1);
            *reinterpret_cast<__half2*>(Es16 + rB*HST + hc) = __floats2half2_rn(vB0, vB1);
            const float2 w2 = *reinterpret_cast<const float2*>(w41s + hc);
            lpA += vA0*w2.x + vA1*w2.y;
            lpB += vB0*w2.x + vB1*w2.y;
        }
        #pragma unroll
        for (int o = 1; o <= 2; o <<= 1) {
            lpA += __shfl_xor_sync(0xffffffffu, lpA, o);
            lpB += __shfl_xor_sync(0xffffffffu, lpB, o);
        }
        if (tig == 0) {
            LG1o[rA] = lpA;
            LG1o[rB] = lpB;
        }
    }

    // --- agg halving reduce over gid lanes (xor 4/8/16); every lane stores 2 ---
    HALVE_ROUND(aggp, 8, 4);
    HALVE_ROUND(aggp, 4, 8);
    HALVE_ROUND(aggp, 2, 16);
    {
        const int nt8 = 4*((lane >> 2) & 1) + 2*((lane >> 3) & 1) + ((lane >> 4) & 1);
        float2 v2 = {aggp[0], aggp[1]};
        *reinterpret_cast<float2*>(wagg + w*64 + nt8*8 + 2*tig) = v2;
    }
    __syncthreads();   // E1 write-out reads ALL warps' Es16 rows

    if (t < NH) {
        float s = 0.f;
        #pragma unroll
        for (int q = 0; q < 8; q++) s += wagg[q*64 + t];
        g_AGG[bi*NH + t] = s;
    }
    // coalesced E1 write-out from staged SMEM
    {
        uint4* Eo = reinterpret_cast<uint4*>(g_E1h + (size_t)bi*NN*NH);
        #pragma unroll
        for (int c = 0; c < 8; c++) {
            int idx = t + 256*c;
            int j = idx >> 3, q = idx & 7;
            Eo[idx] = *reinterpret_cast<const uint4*>(Es16 + j*HST + q*8);
        }
    }
}

// ---------------- layer-1 main kernel (128 rows per block, 4 CTAs/SM) ---------------
__global__ void __launch_bounds__(256, 4) k_main1(const float* __restrict__ W4) {
    extern __shared__ char smc[];
    __half* Es16 = reinterpret_cast<__half*>(smc + K1_ES);
    __half* Wh   = reinterpret_cast<__half*>(smc + K1_W4);
    __half* XJs  = reinterpret_cast<__half*>(smc + K1_XJ);
    float* sA   = reinterpret_cast<float*>(smc + K1_SA);
    float* attA = reinterpret_cast<float*>(smc + K1_ATT);
    float* wagg = reinterpret_cast<float*>(smc + K1_WAGG);
    float* red  = reinterpret_cast<float*>(smc + K1_RED);
    float* red2 = reinterpret_cast<float*>(smc + K1_RED2);

    const int bi   = blockIdx.x >> 1;
    const int half = blockIdx.x & 1;
    const int b  = bi >> 8;
    const int t  = threadIdx.x;
    const int w  = t >> 5;
    const int lane = t & 31;
    const int gid = lane >> 2, tig = lane & 3;

    // E1 + XJ half-slab loads: pure copies -> cp.async (overlap with softmax)
    {
        const uint32_t es_sh = (uint32_t)__cvta_generic_to_shared(Es16);
        const __half* Eg = g_E1h + (size_t)bi*NN*NH + (size_t)half*128*NH;
        #pragma unroll
        for (int c = 0; c < 4; c++) {
            int idx = t + 256*c;
            int j = idx >> 3, q = idx & 7;
            CP_ASYNC16(es_sh + (uint32_t)(j*HST + q*8)*2, Eg + (size_t)idx*8);
        }
        const uint32_t xj_sh = (uint32_t)__cvta_generic_to_shared(XJs);
        const __half* XJg = g_XJh + (size_t)b*NN*NH + (size_t)half*128*NH;
        #pragma unroll
        for (int c = 0; c < 4; c++) {
            int idx = t + 256*c;
            int j = idx >> 3, q = idx & 7;
            CP_ASYNC16(xj_sh + (uint32_t)(j*HST + q*8)*2, XJg + (size_t)idx*8);
        }
        CP_COMMIT();
    }
    // W4 layer-1 slice -> fp16 SMEM (needs conversion; sync loads)
    {
        const float2* Wg2 = reinterpret_cast<const float2*>(W4 + NH*NH);
        #pragma unroll
        for (int c = 0; c < 8; c++) {
            int idx2 = t + 256*c;
            int h = idx2 >> 5, k2 = idx2 & 31;
            float2 vw = Wg2[idx2];
            *reinterpret_cast<__half2*>(Wh + h*HST + 2*k2) = __floats2half2_rn(vw.x, vw.y);
        }
    }
    sA[t] = g_S[b*NN + t];
    __syncthreads();

    // --- softmax over all 256 j (logits precomputed), overlapped with cp.async ---
    float lg = g_LG1[(size_t)bi*NN + t] + g_S[bi] + sA[t];
    float m = lg;
    #pragma unroll
    for (int o = 16; o; o >>= 1) m = fmaxf(m, __shfl_xor_sync(0xffffffffu, m, o));
    if (lane == 0) red[w] = m;
    __syncthreads();
    float mm = red[0];
    #pragma unroll
    for (int q = 1; q < 8; q++) mm = fmaxf(mm, red[q]);
    float ex = __expf(lg - mm);
    float sum = ex;
    #pragma unroll
    for (int o = 16; o; o >>= 1) sum += __shfl_xor_sync(0xffffffffu, sum, o);
    if (lane == 0) red2[w] = sum;
    __syncthreads();
    float s8 = 0.f;
    #pragma unroll
    for (int q = 0; q < 8; q++) s8 += red2[q];
    if ((t >> 7) == half) attA[t & 127] = ex / s8;
    CP_WAIT0();              // E1 + XJ staged before the barrier below
    __syncthreads();

    // --- fp16 tensor GEMM via ldmatrix: warp w -> local rows [w*16, w*16+16) ---
    float acc[8][4];
    #pragma unroll
    for (int nt = 0; nt < 8; nt++)
        #pragma unroll
        for (int q = 0; q < 4; q++) acc[nt][q] = 0.f;

    {
        const uint32_t es_sh = (uint32_t)__cvta_generic_to_shared(Es16);
        const uint32_t wh_sh = (uint32_t)__cvta_generic_to_shared(Wh);
        const int l15 = lane & 15;
        const int lhi = lane >> 4;
        const int l7  = lane & 7;
        const int bsl = (lane >> 3) & 1;
        const uint32_t aAddr = es_sh + (uint32_t)((w*16 + l15)*144 + lhi*16);
        const uint32_t bAddr = wh_sh + (uint32_t)((l7 + 8*lhi)*144 + bsl*16);
        #pragma unroll
        for (int ks = 0; ks < 4; ks++) {
            uint32_t a[4];
            ldsm_x4(a[0], a[1], a[2], a[3], aAddr + 32*ks);
            #pragma unroll
            for (int p = 0; p < 4; p++) {
                uint32_t b0a, b1a, b0b, b1b;
                ldsm_x4(b0a, b1a, b0b, b1b, bAddr + p*16*144 + 32*ks);
                mma_f16(acc[2*p],     a, b0a, b1a);
                mma_f16(acc[2*p + 1], a, b0b, b1b);
            }
        }
    }

    // --- epilogue: att scale + fragment agg (XJ from SMEM) ---
    float aggp[16];
    #pragma unroll
    for (int z = 0; z < 16; z++) aggp[z] = 0.f;
    {
        const int rA = w*16 + gid;
        const int rB = rA + 8;
        const float aA = attA[rA], aB = attA[rB];
        #pragma unroll
        for (int nt = 0; nt < 8; nt++) {
            float e0 = acc[nt][0] * aA;
            float e1 = acc[nt][1] * aA;
            float e2 = acc[nt][2] * aB;
            float e3 = acc[nt][3] * aB;
            const int hc = nt*8 + 2*tig;
            float2 xA = __half22float2(*reinterpret_cast<const __half2*>(XJs + rA*HST + hc));
            float2 xB = __half22float2(*reinterpret_cast<const __half2*>(XJs + rB*HST + hc));
            aggp[2*nt]     += e0*xA.x + e2*xB.x;
            aggp[2*nt + 1] += e1*xA.y + e3*xB.y;
        }
    }
    // halving reduce over gid lanes (xor 4/8/16); every lane stores 2 floats
    HALVE_ROUND(aggp, 8, 4);
    HALVE_ROUND(aggp, 4, 8);
    HALVE_ROUND(aggp, 2, 16);
    {
        const int nt8 = 4*((lane >> 2) & 1) + 2*((lane >> 3) & 1) + ((lane >> 4) & 1);
        float2 v2 = {aggp[0], aggp[1]};
        *reinterpret_cast<float2*>(wagg + w*64 + nt8*8 + 2*tig) = v2;
    }
    __syncthreads();
    if (t < NH) {
        float s = 0.f;
        #pragma unroll
        for (int q = 0; q < 8; q++) s += wagg[q*64 + t];
        g_AGG1[blockIdx.x*NH + t] = s;
    }
}

// ---------------- launch ----------------
extern "C" void kernel_launch(void* const* d_in, const int* in_sizes, int n_in,
                              void* d_out, int out_size) {
    const float* X   = (const float*)d_in[0];
    const float* E   = (const float*)d_in[1];
    const float* W3  = (const float*)d_in[2];
    const float* W4  = (const float*)d_in[3];
    const float* W5  = (const float*)d_in[4];
    const float* W6  = (const float*)d_in[5];
    const float* ng  = (const float*)d_in[6];
    const float* nb  = (const float*)d_in[7];
    const float* eg  = (const float*)d_in[8];
    const float* eb  = (const float*)d_in[9];
    const float* hw1 = (const float*)d_in[10];
    const float* hb1 = (const float*)d_in[11];
    const float* hw2 = (const float*)d_in[12];
    const float* hb2 = (const float*)d_in[13];
    float* out = (float*)d_out;

    cudaFuncSetAttribute(k_main, cudaFuncAttributeMaxDynamicSharedMemorySize,
                         SMEM_MAIN_BYTES);
    cudaFuncSetAttribute(k_main1, cudaFuncAttributeMaxDynamicSharedMemorySize,
                         K1_BYTES);

    k_dummy<<<1, 32>>>();                       // keeps k_main in ncu capture slot
    k_sums<<<1, 128>>>(W3, W4);
    k_xstart<<<NB*NN/8, 512>>>(X, W5, W6);
    k_main<<<NB*NN, 256, SMEM_MAIN_BYTES>>>(E, W4, eg, eb);
    k_xmid<<<NB*NN/8, 512>>>(X, W5, W6, ng, nb);
    k_main1<<<2*NB*NN, 256, K1_BYTES>>>(W4);
    k_final<<<NB*NN/8, 512>>>(ng, nb, hw1, hb1, hw2, hb2, out);
}